// round 16
// baseline (speedup 1.0000x reference)
#include <cuda_runtime.h>
#include <cuda_bf16.h>

#define HW    56
#define TS    68         // row stride: 4-aligned, conflict-free conv banks
#define KSEL  30
#define NT    224        // 2 planes x 112 threads (plane = tid&1)
#define HALF  112
#define TMAXP 256        // candidate capacity per plane
#define PLMAX 448        // row-unit list capacity per plane (= all units)

__global__ __launch_bounds__(NT, 5)
void topk_spatial_kernel(const float* __restrict__ x,
                         const float* __restrict__ wgt,
                         const float* __restrict__ bias,
                         float* __restrict__ out,
                         int C)
{
    __shared__ float tile[2][58 * TS];   // pixel (r,c) of plane p at [p][(r+1)*TS + c+4]
    __shared__ union {                   // hists / candidates: temporally disjoint
        unsigned hist[2][2][256];        // [buf][plane][bin]
        struct { double csc[2][TMAXP]; int cidx[2][TMAXP]; } cand;
    } u;
    __shared__ float    wsm[2][10];
    __shared__ unsigned sh_dsel[2], sh_krem[2];
    __shared__ float    xmax_sm[2][7];
    __shared__ int      tcnt[2], pcnt[2];
    __shared__ int      plist[2][PLMAX]; // flagged row-units: pr*8 + colg

    const int tid  = threadIdx.x;
    const int p    = tid & 1;            // plane
    const int L    = tid >> 1;           // 0..111 within plane
    const int lane = tid & 31;
    const int bc   = blockIdx.x * 2 + p;
    const int ch   = bc % C;
    const float* gx = x   + (size_t)bc * (HW * HW);
    float*       go = out + (size_t)bc * (HW * HW);

    if (tid < 20) {
        int pp = tid / 10, k = tid - pp * 10;
        int chp = (blockIdx.x * 2 + pp) % C;
        wsm[pp][k] = (k < 9) ? wgt[chp * 9 + k] : bias[chp];
    }
    if (tid == 20) { tcnt[0] = 0; tcnt[1] = 0; pcnt[0] = 0; pcnt[1] = 0;
                     sh_krem[0] = KSEL; sh_krem[1] = KSEL; }
    for (int i = tid; i < 512; i += NT) ((unsigned*)u.hist[0])[i] = 0;

    // ---- zero borders of both tiles: rows 0 & 57 full, cols 3 & 60 rows 1..56 ----
    for (int i = tid; i < 496; i += NT) {
        int pl = (i >= 248);
        int j  = i - pl * 248;
        float* T = tile[pl];
        if      (j < 68)  T[j] = 0.f;
        else if (j < 136) T[57 * TS + (j - 68)] = 0.f;
        else if (j < 192) T[(j - 135) * TS + 3] = 0.f;
        else              T[(j - 191) * TS + 60] = 0.f;
    }

    // ---- load interior + zero-fill out; 112 thr/plane, 8 rows/iter x 7 iters ----
    const int r0 = L / 14;               // 0..7
    const int q4 = L - r0 * 14;          // float4 index in row
    float maxv = 0.0f;
    {
        const float4 z4 = make_float4(0.f, 0.f, 0.f, 0.f);
        const float4* gp = reinterpret_cast<const float4*>(gx) + (r0 * 14 + q4);
        float4*       op = reinterpret_cast<float4*>(go)       + (r0 * 14 + q4);
        float*        tp = &tile[p][(r0 + 1) * TS + q4 * 4 + 4];
        #pragma unroll
        for (int it = 0; it < 7; ++it) {
            float4 v = *gp;
            maxv = fmaxf(maxv, fmaxf(fmaxf(fabsf(v.x), fabsf(v.y)),
                                     fmaxf(fabsf(v.z), fabsf(v.w))));
            *reinterpret_cast<float4*>(tp) = v;
            *op = z4;
            gp += 112; op += 112; tp += 8 * TS;
        }
    }
    // per-plane max within warp: butterfly over same-parity lanes (skip d=1)
    #pragma unroll
    for (int d = 2; d <= 16; d <<= 1)
        maxv = fmaxf(maxv, __shfl_xor_sync(0xFFFFFFFFu, maxv, d));
    if (lane < 2) xmax_sm[lane][tid >> 5] = maxv;   // lane==plane parity
    __syncthreads();

    const float w0 = wsm[p][0], w1 = wsm[p][1], w2 = wsm[p][2];
    const float w3 = wsm[p][3], w4 = wsm[p][4], w5 = wsm[p][5];
    const float w6 = wsm[p][6], w7 = wsm[p][7], w8 = wsm[p][8];
    const float bv = wsm[p][9];

    const int rq   = L >> 3;             // 0..13 row-quad
    const int colg = L & 7;              // 0..7 col-group (7 cols each)
    const int row0 = rq * 4;

    // ---- conv: 4x7 patch, 6-row rolling window; track 4 row-unit maxima ----
    float m0 = -3.4e38f, m1 = -3.4e38f, m2 = -3.4e38f, m3 = -3.4e38f;
    {
        const float* R0 = &tile[p][row0 * TS + colg * 7 + 3];
        const float* R1 = R0 + TS;
        const float* R2 = R1 + TS;
        const float* R3 = R2 + TS;
        const float* R4 = R3 + TS;
        const float* R5 = R4 + TS;
        float a00 = R0[0], a01 = R0[1];
        float a10 = R1[0], a11 = R1[1];
        float a20 = R2[0], a21 = R2[1];
        float a30 = R3[0], a31 = R3[1];
        float a40 = R4[0], a41 = R4[1];
        float a50 = R5[0], a51 = R5[1];
        #pragma unroll
        for (int j = 0; j < 7; ++j) {
            float a02 = R0[j + 2], a12 = R1[j + 2], a22 = R2[j + 2];
            float a32 = R3[j + 2], a42 = R4[j + 2], a52 = R5[j + 2];
            float s0 = bv;
            s0 = fmaf(w0, a00, s0); s0 = fmaf(w1, a01, s0); s0 = fmaf(w2, a02, s0);
            s0 = fmaf(w3, a10, s0); s0 = fmaf(w4, a11, s0); s0 = fmaf(w5, a12, s0);
            s0 = fmaf(w6, a20, s0); s0 = fmaf(w7, a21, s0); s0 = fmaf(w8, a22, s0);
            float s1 = bv;
            s1 = fmaf(w0, a10, s1); s1 = fmaf(w1, a11, s1); s1 = fmaf(w2, a12, s1);
            s1 = fmaf(w3, a20, s1); s1 = fmaf(w4, a21, s1); s1 = fmaf(w5, a22, s1);
            s1 = fmaf(w6, a30, s1); s1 = fmaf(w7, a31, s1); s1 = fmaf(w8, a32, s1);
            float s2 = bv;
            s2 = fmaf(w0, a20, s2); s2 = fmaf(w1, a21, s2); s2 = fmaf(w2, a22, s2);
            s2 = fmaf(w3, a30, s2); s2 = fmaf(w4, a31, s2); s2 = fmaf(w5, a32, s2);
            s2 = fmaf(w6, a40, s2); s2 = fmaf(w7, a41, s2); s2 = fmaf(w8, a42, s2);
            float s3 = bv;
            s3 = fmaf(w0, a30, s3); s3 = fmaf(w1, a31, s3); s3 = fmaf(w2, a32, s3);
            s3 = fmaf(w3, a40, s3); s3 = fmaf(w4, a41, s3); s3 = fmaf(w5, a42, s3);
            s3 = fmaf(w6, a50, s3); s3 = fmaf(w7, a51, s3); s3 = fmaf(w8, a52, s3);
            m0 = fmaxf(m0, s0); m1 = fmaxf(m1, s1);
            m2 = fmaxf(m2, s2); m3 = fmaxf(m3, s3);
            a00 = a01; a01 = a02; a10 = a11; a11 = a12;
            a20 = a21; a21 = a22; a30 = a31; a31 = a32;
            a40 = a41; a41 = a42; a50 = a51; a51 = a52;
        }
    }
    const float smax = fmaxf(fmaxf(m0, m1), fmaxf(m2, m3));
    unsigned mu = __float_as_uint(smax);
    const unsigned maxkey = mu ^ ((unsigned)(((int)mu) >> 31) | 0x80000000u);

    // ---- 3-pass radix per plane over its 112 per-thread maxima (disjoint
    //      28-px groups => >=KSEL elements >= M30 => band is a superset) ----
    unsigned prefix = 0;
    #pragma unroll
    for (int pass = 0; pass < 3; ++pass) {
        const int cur   = pass & 1;
        const int shift = 24 - 8 * pass;
        {
            unsigned v  = maxkey;
            bool ok = (((unsigned long long)v) >> (shift + 8)) ==
                      (unsigned long long)prefix;
            unsigned digit = (v >> shift) & 255u;
            unsigned mk = ok ? (digit | ((unsigned)p << 8)) : 0xFFFFFFFFu;
            unsigned m = __match_any_sync(0xFFFFFFFFu, mk);
            if (ok && ((__ffs(m) - 1) == lane))
                atomicAdd(&u.hist[cur][p][digit], (unsigned)__popc(m));
            if (pass < 2)
                for (int i = tid; i < 512; i += NT)
                    ((unsigned*)u.hist[cur ^ 1])[i] = 0;
        }
        __syncthreads();

        if (tid < 64) {                      // warp0 -> plane0, warp1 -> plane1
            int pl = tid >> 5, ln = tid & 31;
            unsigned kr = sh_krem[pl];
            __syncwarp();
            unsigned loc[8];
            unsigned run = 0;
            #pragma unroll
            for (int j = 7; j >= 0; --j) { run += u.hist[cur][pl][ln * 8 + j]; loc[j] = run; }
            unsigned laneTotal = run;
            unsigned incl = laneTotal;
            #pragma unroll
            for (int d = 1; d < 32; d <<= 1) {
                unsigned t = __shfl_down_sync(0xFFFFFFFFu, incl, d);
                if (ln + d < 32) incl += t;
            }
            unsigned hiSum = incl - laneTotal;
            #pragma unroll
            for (int j = 0; j < 8; ++j) {
                unsigned suf  = hiSum + loc[j];
                unsigned sufn = (j < 7) ? (hiSum + loc[j + 1]) : hiSum;
                if (suf >= kr && sufn < kr) {
                    sh_dsel[pl] = (unsigned)(ln * 8 + j);
                    sh_krem[pl] = kr - sufn;
                }
            }
        }
        __syncthreads();
        prefix = (prefix << 8) | sh_dsel[p];
    }
    const unsigned MtruncKey = prefix << 8;  // lower bound of M30's key block

    // ---- guard band: Tc = float(trunc24(M30)) - 2E (per plane) ----
    float xmax = xmax_sm[p][0];
    #pragma unroll
    for (int i = 1; i < 7; ++i) xmax = fmaxf(xmax, xmax_sm[p][i]);
    const float wsum = fabsf(w0) + fabsf(w1) + fabsf(w2) + fabsf(w3) + fabsf(w4)
                     + fabsf(w5) + fabsf(w6) + fabsf(w7) + fabsf(w8);
    const float E = (wsum * xmax + fabsf(bv)) * 1.2e-6f;
    unsigned tu = (MtruncKey & 0x80000000u) ? (MtruncKey ^ 0x80000000u) : ~MtruncKey;
    const float Tc = __uint_as_float(tu) - 2.0f * E;

    // ---- Phase A0: flag 1x7 row-units whose max clears the band ----
    {
        int base = row0 * 8 + colg;          // unit id = pr*8 + colg
        if (m0 >= Tc) { int q = atomicAdd(&pcnt[p], 1); if (q < PLMAX) plist[p][q] = base;      }
        if (m1 >= Tc) { int q = atomicAdd(&pcnt[p], 1); if (q < PLMAX) plist[p][q] = base + 8;  }
        if (m2 >= Tc) { int q = atomicAdd(&pcnt[p], 1); if (q < PLMAX) plist[p][q] = base + 16; }
        if (m3 >= Tc) { int q = atomicAdd(&pcnt[p], 1); if (q < PLMAX) plist[p][q] = base + 24; }
    }
    __syncthreads();
    const int np = (pcnt[p] < PLMAX) ? pcnt[p] : PLMAX;

    // ---- Phase A1 (+fused B): cooperative rescore of flagged units' pixels;
    //      on a hit the 9 taps are in registers -> exact double score now ----
    for (int idx = L; idx < np * 7; idx += HALF) {
        int qq   = idx / 7;
        int k    = idx - qq * 7;
        int unit = plist[p][qq];
        int pr   = unit >> 3;
        int pc   = (unit & 7) * 7 + k;
        const float* t0 = &tile[p][pr * TS + pc + 3];
        float v0 = t0[0],    v1 = t0[1],      v2 = t0[2];
        float v3 = t0[TS],   v4 = t0[TS + 1], v5 = t0[TS + 2];
        float v6 = t0[2*TS], v7 = t0[2*TS+1], v8 = t0[2*TS+2];
        float s = bv;
        s = fmaf(w0, v0, s); s = fmaf(w1, v1, s); s = fmaf(w2, v2, s);
        s = fmaf(w3, v3, s); s = fmaf(w4, v4, s); s = fmaf(w5, v5, s);
        s = fmaf(w6, v6, s); s = fmaf(w7, v7, s); s = fmaf(w8, v8, s);
        if (s >= Tc) {
            double d = (double)bv;
            d = fma((double)w0, (double)v0, d);
            d = fma((double)w1, (double)v1, d);
            d = fma((double)w2, (double)v2, d);
            d = fma((double)w3, (double)v3, d);
            d = fma((double)w4, (double)v4, d);
            d = fma((double)w5, (double)v5, d);
            d = fma((double)w6, (double)v6, d);
            d = fma((double)w7, (double)v7, d);
            d = fma((double)w8, (double)v8, d);
            int pos = atomicAdd(&tcnt[p], 1);
            if (pos < TMAXP) { u.cand.csc[p][pos] = d; u.cand.cidx[p][pos] = pr * HW + pc; }
        }
    }
    __syncthreads();
    const int ntie = (tcnt[p] < TMAXP) ? tcnt[p] : TMAXP;

    // ---- Phase C: rank by (double desc, index asc); winners scatter into the
    //      pre-zeroed output (ordered after zero STGs by the barriers above) ----
    if (L < ntie) {
        double mys = u.cand.csc[p][L];
        int   cpos = u.cand.cidx[p][L];
        unsigned rnk = 0;
        for (int qq = 0; qq < ntie; ++qq) {
            double v = u.cand.csc[p][qq];
            rnk += (v > mys) || (v == mys && u.cand.cidx[p][qq] < cpos);
        }
        if (rnk < KSEL) {
            int r = cpos / HW, cc = cpos - r * HW;
            go[cpos] = tile[p][(r + 1) * TS + cc + 4];
        }
    }
}

extern "C" void kernel_launch(void* const* d_in, const int* in_sizes, int n_in,
                              void* d_out, int out_size)
{
    const float* x  = (const float*)d_in[0];
    const float* w  = (const float*)d_in[1];
    const float* b  = (const float*)d_in[2];
    float*       o  = (float*)d_out;
    int C    = in_sizes[2];               // 384
    int n_bc = in_sizes[0] / (HW * HW);   // 12288
    topk_spatial_kernel<<<n_bc / 2, NT>>>(x, w, b, o, C);
}